// round 3
// baseline (speedup 1.0000x reference)
#include <cuda_runtime.h>
#include <math.h>

// Problem constants (fixed by reference setup_inputs)
#define Bn     8
#define Dn     128
#define Hn     256
#define Wn     256
#define HWn    (Hn * Wn)
#define NBn    15
#define HALFn  7
#define NSn    256
#define PATCHn (NBn * NBn)   // 225
#define TEMPc  0.07f
#define EPSc   1e-8f

// Per-anchor scratch (no device allocation allowed; use __device__ globals).
// Every slot is written unconditionally by anchor_kernel, so no init needed.
__device__ float g_loss[Bn * NSn];
__device__ int   g_valid[Bn * NSn];

__device__ __forceinline__ float warpReduceSum(float v) {
#pragma unroll
    for (int o = 16; o > 0; o >>= 1)
        v += __shfl_xor_sync(0xffffffffu, v, o);
    return v;
}

__device__ __forceinline__ float warpReduceMax(float v) {
#pragma unroll
    for (int o = 16; o > 0; o >>= 1)
        v = fmaxf(v, __shfl_xor_sync(0xffffffffu, v, o));
    return v;
}

// One CTA per anchor. 256 threads; thread t < 225 owns patch cell (k,l).
__global__ __launch_bounds__(256, 4)
void anchor_kernel(const float* __restrict__ feat,
                   const int*   __restrict__ targ,
                   const int*   __restrict__ ahp,
                   const int*   __restrict__ awp) {
    const int bid  = blockIdx.x;          // = b * NSn + n  (arrays are [B, NS] row-major)
    const int b    = bid >> 8;            // NSn == 256
    const int t    = threadIdx.x;
    const int wid  = t >> 5;
    const int lane = t & 31;

    __shared__ float s_af[Dn];
    __shared__ float red[8];
    __shared__ float red3[3][8];
    __shared__ float s_bcast;

    const int ah = ahp[bid];
    const int aw = awp[bid];
    const float* __restrict__ fb = feat + (size_t)b * Dn * HWn;
    const int*   __restrict__ tb = targ + b * HWn;
    const int center = ah * Wn + aw;

    // ---- anchor feature vector -> smem, and its squared norm ----
    float asq = 0.f;
    if (t < Dn) {
        float v = __ldg(fb + (size_t)t * HWn + center);
        s_af[t] = v;
        asq = v * v;
    }
    {
        float ws = warpReduceSum(asq);
        if (lane == 0) red[wid] = ws;
    }
    __syncthreads();
    if (t == 0) {
        float s = 0.f;
#pragma unroll
        for (int i = 0; i < 8; ++i) s += red[i];
        s_bcast = fmaxf(sqrtf(s), EPSc);
    }
    __syncthreads();
    const float an   = s_bcast;
    const int   alab = __ldg(tb + center);

    // ---- per-patch-cell dot product + patch norm ----
    float sim = -INFINITY;
    bool  pos = false;
    if (t < PATCHn) {
        const int k = t / NBn;
        const int l = t - k * NBn;
        const int pidx = center + (k - HALFn) * Wn + (l - HALFn);
        pos = (__ldg(tb + pidx) == alab) && (t != (HALFn * NBn + HALFn));

        const float* __restrict__ p = fb + pidx;
        float dot = 0.f, pn = 0.f;
#pragma unroll 8
        for (int d = 0; d < Dn; ++d) {
            float v = __ldg(p + (size_t)d * HWn);
            dot = fmaf(s_af[d], v, dot);
            pn  = fmaf(v, v, pn);
        }
        const float pnorm = fmaxf(sqrtf(pn), EPSc);
        sim = dot / (an * pnorm * TEMPc);
    }
    __syncthreads();   // red / s_bcast reuse barrier

    // ---- block max over 225 sims ----
    {
        float m = warpReduceMax(sim);
        if (lane == 0) red[wid] = m;
    }
    __syncthreads();
    if (t == 0) {
        float x = red[0];
#pragma unroll
        for (int i = 1; i < 8; ++i) x = fmaxf(x, red[i]);
        s_bcast = x;
    }
    __syncthreads();
    const float m = s_bcast;

    // ---- sumexp, positive sum, positive count (single sync, 3 lanes of smem) ----
    const float e  = (t < PATCHn) ? __expf(sim - m) : 0.f;
    const float pv = pos ? sim : 0.f;
    const float pc = pos ? 1.f : 0.f;
    {
        float se = warpReduceSum(e);
        float ps = warpReduceSum(pv);
        float cc = warpReduceSum(pc);
        if (lane == 0) { red3[0][wid] = se; red3[1][wid] = ps; red3[2][wid] = cc; }
    }
    __syncthreads();
    if (t == 0) {
        float S = 0.f, P = 0.f, C = 0.f;
#pragma unroll
        for (int i = 0; i < 8; ++i) { S += red3[0][i]; P += red3[1][i]; C += red3[2][i]; }
        const float lse = m + logf(S);
        const int cnt = (int)(C + 0.5f);
        float loss = 0.f;
        int   val  = 0;
        if (cnt > 0) {
            loss = -(P / (float)cnt - lse);
            val  = 1;
        }
        g_loss[bid]  = loss;
        g_valid[bid] = val;
    }
}

// Deterministic final reduction of 2048 per-anchor partials into the scalar.
__global__ __launch_bounds__(256)
void finalize_kernel(float* __restrict__ out) {
    const int t = threadIdx.x;
    float s = 0.f, c = 0.f;
#pragma unroll
    for (int i = t; i < Bn * NSn; i += 256) {
        s += g_loss[i];
        c += (float)g_valid[i];
    }
    __shared__ float r1[8], r2[8];
    const int wid = t >> 5, lane = t & 31;
    float ws = warpReduceSum(s);
    float wc = warpReduceSum(c);
    if (lane == 0) { r1[wid] = ws; r2[wid] = wc; }
    __syncthreads();
    if (t == 0) {
        float S = 0.f, C = 0.f;
#pragma unroll
        for (int i = 0; i < 8; ++i) { S += r1[i]; C += r2[i]; }
        const int cnt = (int)(C + 0.5f);
        out[0] = (cnt > 0) ? (S / (float)cnt) : 0.f;
    }
}

extern "C" void kernel_launch(void* const* d_in, const int* in_sizes, int n_in,
                              void* d_out, int out_size) {
    const float* feat = (const float*)d_in[0];  // (8,128,256,256) f32
    const int*   targ = (const int*)  d_in[1];  // (8,256,256) i32
    const int*   ah   = (const int*)  d_in[2];  // (8,256) i32
    const int*   aw   = (const int*)  d_in[3];  // (8,256) i32
    float* out = (float*)d_out;

    anchor_kernel<<<Bn * NSn, 256>>>(feat, targ, ah, aw);
    finalize_kernel<<<1, 256>>>(out);
}

// round 4
// speedup vs baseline: 1.0356x; 1.0356x over previous
#include <cuda_runtime.h>
#include <math.h>

// Problem constants (fixed by reference setup_inputs)
#define Bn     8
#define Dn     128
#define Hn     256
#define Wn     256
#define HWn    (Hn * Wn)
#define NBn    15
#define HALFn  7
#define NSn    256
#define PATCHn (NBn * NBn)   // 225
#define NANCH  (Bn * NSn)    // 2048
#define TEMPc  0.07f
#define EPSc   1e-8f

// Per-anchor scratch (device allocation is forbidden; __device__ globals only).
// Every slot is written unconditionally each launch before being read.
__device__ float        g_loss[NANCH];
__device__ float        g_validf[NANCH];
__device__ unsigned int g_ticket;   // zero-initialized at module load; reset to 0 by last block

__device__ __forceinline__ float warpReduceSum(float v) {
#pragma unroll
    for (int o = 16; o > 0; o >>= 1)
        v += __shfl_xor_sync(0xffffffffu, v, o);
    return v;
}

__device__ __forceinline__ float warpReduceMax(float v) {
#pragma unroll
    for (int o = 16; o > 0; o >>= 1)
        v = fmaxf(v, __shfl_xor_sync(0xffffffffu, v, o));
    return v;
}

// One CTA per anchor. 256 threads; thread t < 225 owns patch cell (k,l).
// The last CTA to finish folds the 2048 per-anchor partials into the scalar.
__global__ __launch_bounds__(256, 4)
void anchor_kernel(const float* __restrict__ feat,
                   const int*   __restrict__ targ,
                   const int*   __restrict__ ahp,
                   const int*   __restrict__ awp,
                   float*       __restrict__ out) {
    const int bid  = blockIdx.x;          // = b * NSn + n  (arrays are [B, NS] row-major)
    const int b    = bid >> 8;            // NSn == 256
    const int t    = threadIdx.x;
    const int wid  = t >> 5;
    const int lane = t & 31;

    __shared__ float s_af[Dn];
    __shared__ float red[8];
    __shared__ float red3[3][8];
    __shared__ float s_bcast;
    __shared__ int   s_last;

    const int ah = ahp[bid];
    const int aw = awp[bid];
    const float* __restrict__ fb = feat + (size_t)b * Dn * HWn;
    const int*   __restrict__ tb = targ + b * HWn;
    const int center = ah * Wn + aw;

    // ---- anchor feature vector -> smem, and its squared norm ----
    float asq = 0.f;
    if (t < Dn) {
        float v = __ldg(fb + (size_t)t * HWn + center);
        s_af[t] = v;
        asq = v * v;
    }
    {
        float ws = warpReduceSum(asq);
        if (lane == 0) red[wid] = ws;
    }
    __syncthreads();
    if (t == 0) {
        float s = 0.f;
#pragma unroll
        for (int i = 0; i < 8; ++i) s += red[i];
        s_bcast = fmaxf(sqrtf(s), EPSc);
    }
    __syncthreads();
    const float an   = s_bcast;
    const int   alab = __ldg(tb + center);

    // ---- per-patch-cell dot product + patch norm (16-deep MLP) ----
    float sim = -INFINITY;
    bool  pos = false;
    if (t < PATCHn) {
        const int k = t / NBn;
        const int l = t - k * NBn;
        const int pidx = center + (k - HALFn) * Wn + (l - HALFn);
        pos = (__ldg(tb + pidx) == alab) && (t != (HALFn * NBn + HALFn));

        const float* __restrict__ p = fb + pidx;
        float dot = 0.f, pn = 0.f;
#pragma unroll 16
        for (int d = 0; d < Dn; ++d) {
            float v = __ldg(p + (size_t)d * HWn);
            dot = fmaf(s_af[d], v, dot);
            pn  = fmaf(v, v, pn);
        }
        const float pnorm = fmaxf(sqrtf(pn), EPSc);
        sim = dot / (an * pnorm * TEMPc);
    }
    __syncthreads();   // red / s_bcast reuse barrier

    // ---- block max over 225 sims ----
    {
        float m = warpReduceMax(sim);
        if (lane == 0) red[wid] = m;
    }
    __syncthreads();
    if (t == 0) {
        float x = red[0];
#pragma unroll
        for (int i = 1; i < 8; ++i) x = fmaxf(x, red[i]);
        s_bcast = x;
    }
    __syncthreads();
    const float m = s_bcast;

    // ---- sumexp, positive sum, positive count ----
    const float e  = (t < PATCHn) ? __expf(sim - m) : 0.f;
    const float pv = pos ? sim : 0.f;
    const float pc = pos ? 1.f : 0.f;
    {
        float se = warpReduceSum(e);
        float ps = warpReduceSum(pv);
        float cc = warpReduceSum(pc);
        if (lane == 0) { red3[0][wid] = se; red3[1][wid] = ps; red3[2][wid] = cc; }
    }
    __syncthreads();
    if (t == 0) {
        float S = 0.f, P = 0.f, C = 0.f;
#pragma unroll
        for (int i = 0; i < 8; ++i) { S += red3[0][i]; P += red3[1][i]; C += red3[2][i]; }
        const float lse = m + logf(S);
        const int cnt = (int)(C + 0.5f);
        float loss = 0.f, val = 0.f;
        if (cnt > 0) {
            loss = -(P / (float)cnt - lse);
            val  = 1.f;
        }
        g_loss[bid]   = loss;
        g_validf[bid] = val;

        // Publish, then grab a ticket. The CTA drawing the last ticket reduces.
        __threadfence();
        unsigned int tk = atomicAdd(&g_ticket, 1u);
        s_last = (tk == (unsigned int)(gridDim.x - 1)) ? 1 : 0;
    }
    __syncthreads();

    // ---- last CTA: deterministic final reduction over 2048 partials ----
    if (s_last) {
        float s = 0.f, c = 0.f;
#pragma unroll
        for (int i = t; i < NANCH; i += 256) {
            s += __ldcg(&g_loss[i]);     // .cg: bypass (possibly stale) L1
            c += __ldcg(&g_validf[i]);
        }
        float ws = warpReduceSum(s);
        float wc = warpReduceSum(c);
        if (lane == 0) { red3[0][wid] = ws; red3[1][wid] = wc; }
        __syncthreads();
        if (t == 0) {
            float S = 0.f, C = 0.f;
#pragma unroll
            for (int i = 0; i < 8; ++i) { S += red3[0][i]; C += red3[1][i]; }
            const int cnt = (int)(C + 0.5f);
            out[0] = (cnt > 0) ? (S / (float)cnt) : 0.f;
            g_ticket = 0;   // reset for next graph replay (deterministic)
        }
    }
}

extern "C" void kernel_launch(void* const* d_in, const int* in_sizes, int n_in,
                              void* d_out, int out_size) {
    const float* feat = (const float*)d_in[0];  // (8,128,256,256) f32
    const int*   targ = (const int*)  d_in[1];  // (8,256,256) i32
    const int*   ah   = (const int*)  d_in[2];  // (8,256) i32
    const int*   aw   = (const int*)  d_in[3];  // (8,256) i32
    float* out = (float*)d_out;

    anchor_kernel<<<NANCH, 256>>>(feat, targ, ah, aw, out);
}